// round 13
// baseline (speedup 1.0000x reference)
#include <cuda_runtime.h>
#include <cuda_fp16.h>
#include <cstdint>

#define TOKENS 256
#define NOUT 4096
#define NIN 4096
#define NSPARSE 8388608

// ---------------- GEMM tiling (fp16 mma.sync m16n8k16; R5 config, at legacy HMMA cap) ----------------
#define BM 64
#define BN 64
#define BK 64                         // halfs per K-stage = 128 bytes (one swizzle row)
#define STAGES 4
#define NS (NIN / BK)                 // 64 K-stages
#define GTHREADS 128                  // gemm half: 4 warps, 2(M) x 2(N), warp tile 32x32

#define A_BYTES (BM * 128)            // 8 KB
#define B_BYTES (BN * 128)            // 8 KB
#define STAGE_BYTES (A_BYTES + B_BYTES)
#define SMEM_TOTAL (STAGES * STAGE_BYTES)   // 64 KB dynamic

// ---------------- prep partitioning ----------------
#define WARP_NZ 256                         // nz per chunk (64 quads, 2 per lane)
#define NCHUNK (NSPARSE / WARP_NZ)          // 32768 chunks
#define PREP_WARPS 1024                     // 256 CTAs x 4 prep warps
#define PASSES (NCHUNK / PREP_WARPS)        // 32 chunks per prep warp
#define SW_CAP 1280                         // smem halves per warp window (span 512 +- 24 sigma)
#define XQ_PER_CTA 1024                     // 262144 x-quads / 256 CTAs

// groups: W rows [g*64,(g+1)*64) == flat [g<<18,(g+1)<<18); group == GEMM nbase tile
#define GSHIFT 18
#define NGROUPS 64
#define NCTAS 256

// ---------------- persistent device scratch (zero-init at module load) ----------------
__device__ __half g_W[NOUT * NIN];     // 32 MB fp16 weight; untouched entries stay 0 forever
__device__ __half g_xh[TOKENS * NIN];  // 2 MB fp16 activations
__device__ int    g_done[NGROUPS];     // chunks completed per group (self-resetting per launch)
__device__ int    g_xcnt;              // x-convert slices completed
__device__ int    g_fin;               // finished kernel-halves (512 -> reset)

// ---------------- helpers ----------------
__device__ __forceinline__ uint32_t s2u(const void* p) {
    uint32_t a;
    asm("{ .reg .u64 t; cvta.to.shared.u64 t, %1; cvt.u32.u64 %0, t; }" : "=r"(a) : "l"(p));
    return a;
}

__device__ __forceinline__ void cpasync16(uint32_t saddr, const void* g) {
    asm volatile("cp.async.cg.shared.global [%0], [%1], 16;" :: "r"(saddr), "l"(g) : "memory");
}
#define CP_COMMIT() asm volatile("cp.async.commit_group;" ::: "memory")
#define CP_WAIT()   asm volatile("cp.async.wait_group %0;" :: "n"(STAGES - 2) : "memory")
#define GBAR()      asm volatile("bar.sync 1, 128;" ::: "memory")   // gemm half barrier
#define PBAR()      asm volatile("bar.sync 2, 128;" ::: "memory")   // prep half barrier

__device__ __forceinline__ void ldsm4(uint32_t& r0, uint32_t& r1, uint32_t& r2, uint32_t& r3,
                                      uint32_t addr) {
    asm volatile("ldmatrix.sync.aligned.m8n8.x4.shared.b16 {%0,%1,%2,%3}, [%4];"
                 : "=r"(r0), "=r"(r1), "=r"(r2), "=r"(r3) : "r"(addr));
}

__device__ __forceinline__ void mma16(float* d, const uint32_t* a, uint32_t b0, uint32_t b1) {
    asm volatile(
        "mma.sync.aligned.m16n8k16.row.col.f32.f16.f16.f32 "
        "{%0,%1,%2,%3}, {%4,%5,%6,%7}, {%8,%9}, {%0,%1,%2,%3};"
        : "+f"(d[0]), "+f"(d[1]), "+f"(d[2]), "+f"(d[3])
        : "r"(a[0]), "r"(a[1]), "r"(a[2]), "r"(a[3]), "r"(b0), "r"(b1));
}

// last of 512 finishing halves resets counters -> every launch (incl. graph replays) starts clean
__device__ __forceinline__ void finish_half() {
    __threadfence();
    int f = atomicAdd(&g_fin, 1);
    if (f == 2 * NCTAS - 1) {
        #pragma unroll
        for (int g = 0; g < NGROUPS; g++) g_done[g] = 0;
        g_xcnt = 0;
        __threadfence();
        g_fin = 0;
        __threadfence();
    }
}

// ---------------- stage load: gmem -> swizzled smem via cp.async (gemm half, tid 0..127) ----------------
__device__ __forceinline__ void load_stage(uint32_t sb, int mbase, int nbase, int stage, int tid) {
    int slot = stage & (STAGES - 1);
    int k0 = stage * BK;
    uint32_t abase = sb + slot * STAGE_BYTES;
    uint32_t bbase = abase + A_BYTES;
    #pragma unroll
    for (int i = 0; i < 4; i++) {
        int q = tid + i * GTHREADS;
        int row = q >> 3, c = q & 7;
        const __half* g = g_xh + (mbase + row) * NIN + k0 + c * 8;
        uint32_t off = row * 128 + c * 16;
        cpasync16(abase + (off ^ ((off >> 3) & 0x70)), g);
    }
    #pragma unroll
    for (int i = 0; i < 4; i++) {
        int q = tid + i * GTHREADS;
        int row = q >> 3, c = q & 7;
        const __half* g = g_W + (size_t)(nbase + row) * NIN + k0 + c * 8;
        uint32_t off = row * 128 + c * 16;
        cpasync16(bbase + (off ^ ((off >> 3) & 0x70)), g);
    }
}

// ---------------- fused kernel: prep (warps 4-7) + GEMM (warps 0-3), overlapped ----------------
__global__ void __launch_bounds__(256, 2) fused_kernel(const float4* __restrict__ x,
                                                       const float4* __restrict__ vals,
                                                       const int4* __restrict__ idx,
                                                       float* __restrict__ out) {
    extern __shared__ char smem[];                      // 64 KB gemm stages
    __shared__ __align__(16) __half swin[4 * SW_CAP];   // 10 KB prep windows
    int tid = threadIdx.x;
    int bi = blockIdx.x;

    if (tid >= 128) {
        // ================= PREP HALF =================
        int t = tid - 128;
        // 1) x slice: 1024 quads, 8 per thread
        {
            int base = bi * XQ_PER_CTA;
            __half2* o = reinterpret_cast<__half2*>(g_xh);
            #pragma unroll
            for (int j = 0; j < 8; j++) {
                int i = base + t + j * 128;
                float4 v = x[i];
                o[2 * i]     = __float22half2_rn(make_float2(v.x, v.y));
                o[2 * i + 1] = __float22half2_rn(make_float2(v.z, v.w));
            }
        }
        PBAR();
        __threadfence();
        if (t == 0) atomicAdd(&g_xcnt, 1);

        // 2) scatter chunks in globally striped (group) order
        int wid = t >> 5, lane = t & 31;
        int pw = bi * 4 + wid;                  // global prep-warp id (0..1023)
        __half* s = swin + wid * SW_CAP;
        for (int p = 0; p < PASSES; p++) {
            int ch = p * PREP_WARPS + pw;       // pass p covers contiguous chunks -> group order
            int q0 = ch * 64 + lane;
            float4 v0 = vals[q0];
            float4 v1 = vals[q0 + 32];
            int4 id0 = idx[q0];
            int4 id1 = idx[q0 + 32];
            int lo = __shfl_sync(0xFFFFFFFFu, id0.x, 0);
            int hi = __shfl_sync(0xFFFFFFFFu, id1.w, 31);
            int sbase = lo & ~7;
            int span = hi - sbase + 1;

            if (span <= SW_CAP) {
                int zq = ((span + 7) & ~7) >> 3;
                int4* s4 = reinterpret_cast<int4*>(s);
                int4 z = make_int4(0, 0, 0, 0);
                for (int i = lane; i < zq; i += 32) s4[i] = z;
                __syncwarp();
                s[id0.x - sbase] = __float2half_rn(v0.x);
                s[id0.y - sbase] = __float2half_rn(v0.y);
                s[id0.z - sbase] = __float2half_rn(v0.z);
                s[id0.w - sbase] = __float2half_rn(v0.w);
                s[id1.x - sbase] = __float2half_rn(v1.x);
                s[id1.y - sbase] = __float2half_rn(v1.y);
                s[id1.z - sbase] = __float2half_rn(v1.z);
                s[id1.w - sbase] = __float2half_rn(v1.w);
                __syncwarp();
                int cstart = (lo + 7) >> 3;
                int cend = (hi + 1) >> 3;
                int4* w4 = reinterpret_cast<int4*>(g_W);
                for (int c2 = cstart + lane; c2 < cend; c2 += 32)
                    w4[c2] = *reinterpret_cast<int4*>(s + (c2 * 8 - sbase));
                int fp = cstart * 8 - lo;
                if (lane < fp) g_W[lo + lane] = s[(lo - sbase) + lane];
                int bp = hi + 1 - cend * 8;
                if (lane >= 8 && lane < 8 + bp) {
                    int pos = cend * 8 + (lane - 8);
                    g_W[pos] = s[pos - sbase];
                }
            } else {
                // statistical impossibility fallback
                g_W[id0.x] = __float2half_rn(v0.x);
                g_W[id0.y] = __float2half_rn(v0.y);
                g_W[id0.z] = __float2half_rn(v0.z);
                g_W[id0.w] = __float2half_rn(v0.w);
                g_W[id1.x] = __float2half_rn(v1.x);
                g_W[id1.y] = __float2half_rn(v1.y);
                g_W[id1.z] = __float2half_rn(v1.z);
                g_W[id1.w] = __float2half_rn(v1.w);
            }
            // signal every group this chunk intersects (1 or 2)
            __threadfence();
            __syncwarp();
            if (lane == 0) {
                int g0 = lo >> GSHIFT, g1 = hi >> GSHIFT;
                for (int g = g0; g <= g1; g++) atomicAdd(&g_done[g], 1);
            }
        }
        PBAR();
        if (t == 0) finish_half();
        return;
    }

    // ================= GEMM HALF (tid 0..127) =================
    int grp = bi >> 2;                  // group == nbase tile
    int mbase = (bi & 3) * BM;
    int nbase = grp * BN;

    if (tid == 0) {
        // expected chunk count for this group (two binary searches on sorted idx)
        int glo = grp << GSHIFT;
        int gend = (grp + 1) << GSHIFT;
        const int* idxs = (const int*)idx;
        int a = 0, b = NCHUNK - 1;
        while (a < b) { int m = (a + b) >> 1; if (idxs[m * WARP_NZ + (WARP_NZ - 1)] >= glo) b = m; else a = m + 1; }
        int cf = a;
        a = 0; b = NCHUNK - 1;
        while (a < b) { int m = (a + b + 1) >> 1; if (idxs[m * WARP_NZ] < gend) a = m; else b = m - 1; }
        int total = a - cf + 1;
        if (total < 0) total = 0;
        if (total > NCHUNK) total = NCHUNK;
        // >= spins: any over-count degrades to early start, never an infinite spin
        while (*(volatile int*)&g_xcnt < NCTAS) __nanosleep(100);
        while (*(volatile int*)&g_done[grp] < total) __nanosleep(100);
        __threadfence();
    }
    GBAR();

    uint32_t sb = s2u(smem);
    int lane = tid & 31;
    int wid = tid >> 5;
    int wm = wid >> 1;
    int wn = wid & 1;
    int lr = lane & 7;
    int lq = lane >> 3;

    uint32_t arow[2], axor[2];
    #pragma unroll
    for (int mt = 0; mt < 2; mt++) {
        uint32_t r = wm * 32 + mt * 16 + (lq & 1) * 8 + lr;
        arow[mt] = r * 128;
        axor[mt] = (r & 7) << 4;
    }
    uint32_t acol = (lq >> 1) * 16;
    uint32_t brow[2], bxor[2];
    #pragma unroll
    for (int p = 0; p < 2; p++) {
        uint32_t r = wn * 32 + p * 16 + (lq >> 1) * 8 + lr;
        brow[p] = r * 128;
        bxor[p] = (r & 7) << 4;
    }
    uint32_t bcol = (lq & 1) * 16;

    float acc[2][4][4];
    #pragma unroll
    for (int mt = 0; mt < 2; mt++)
        #pragma unroll
        for (int nt = 0; nt < 4; nt++)
            #pragma unroll
            for (int j = 0; j < 4; j++) acc[mt][nt][j] = 0.0f;

    #pragma unroll
    for (int l = 0; l < STAGES - 1; l++) {
        load_stage(sb, mbase, nbase, l, tid);
        CP_COMMIT();
    }

    for (int s = 0; s < NS; s++) {
        int slot = s & (STAGES - 1);
        CP_WAIT();
        GBAR();

        if (s + STAGES - 1 < NS) load_stage(sb, mbase, nbase, s + STAGES - 1, tid);
        CP_COMMIT();

        uint32_t aBase = sb + slot * STAGE_BYTES;
        uint32_t bBase = aBase + A_BYTES;

        #pragma unroll
        for (int ks = 0; ks < 4; ks++) {
            uint32_t a[2][4], b[2][4];
            #pragma unroll
            for (int mt = 0; mt < 2; mt++)
                ldsm4(a[mt][0], a[mt][1], a[mt][2], a[mt][3],
                      aBase + arow[mt] + ((ks * 32 + acol) ^ axor[mt]));
            #pragma unroll
            for (int p = 0; p < 2; p++)
                ldsm4(b[p][0], b[p][1], b[p][2], b[p][3],
                      bBase + brow[p] + ((ks * 32 + bcol) ^ bxor[p]));
            #pragma unroll
            for (int mt = 0; mt < 2; mt++) {
                #pragma unroll
                for (int nt = 0; nt < 4; nt++) {
                    const uint32_t* bp = b[nt >> 1];
                    mma16(acc[mt][nt], a[mt], bp[(nt & 1) * 2], bp[(nt & 1) * 2 + 1]);
                }
            }
        }
    }

    int g = lane >> 2, tg = lane & 3;
    #pragma unroll
    for (int mt = 0; mt < 2; mt++) {
        #pragma unroll
        for (int nt = 0; nt < 4; nt++) {
            int row = mbase + wm * 32 + mt * 16 + g;
            int col = nbase + wn * 32 + nt * 8 + tg * 2;
            float2* p0 = reinterpret_cast<float2*>(out + (size_t)row * NOUT + col);
            float2* p1 = reinterpret_cast<float2*>(out + (size_t)(row + 8) * NOUT + col);
            *p0 = make_float2(acc[mt][nt][0], acc[mt][nt][1]);
            *p1 = make_float2(acc[mt][nt][2], acc[mt][nt][3]);
        }
    }
    GBAR();
    if (tid == 0) finish_half();
}

// ---------------- launch ----------------
extern "C" void kernel_launch(void* const* d_in, const int* in_sizes, int n_in,
                              void* d_out, int out_size) {
    const float* x    = (const float*)d_in[0];
    const float* vals = (const float*)d_in[1];
    const int*   idx  = (const int*)d_in[2];
    float* out = (float*)d_out;
    (void)in_sizes; (void)n_in; (void)out_size;

    cudaFuncSetAttribute(fused_kernel, cudaFuncAttributeMaxDynamicSharedMemorySize, SMEM_TOTAL);

    // 256 CTAs (= NGROUPS * 4 m-tiles), 2 resident per SM, ALL co-resident in wave 1
    fused_kernel<<<NCTAS, 256, SMEM_TOTAL>>>((const float4*)x, (const float4*)vals,
                                             (const int4*)idx, out);
}

// round 14
// speedup vs baseline: 2.0944x; 2.0944x over previous
#include <cuda_runtime.h>
#include <cuda_fp16.h>
#include <cstdint>

#define TOKENS 256
#define NOUT 4096
#define NIN 4096
#define NSPARSE 8388608

// ---------------- GEMM tiling (fp16 mma.sync m16n8k16; R5 config, near HMMA cap) ----------------
#define BM 64
#define BN 64
#define BK 64                         // halfs per K-stage = 128 bytes (one swizzle row)
#define STAGES 4
#define NS (NIN / BK)                 // 64 K-stages
#define NTHREADS 128                  // 4 warps: 2 (M) x 2 (N), warp tile 32x32

#define A_BYTES (BM * 128)            // 8 KB
#define B_BYTES (BN * 128)            // 8 KB
#define STAGE_BYTES (A_BYTES + B_BYTES)
#define SMEM_TOTAL (STAGES * STAGE_BYTES)   // 64 KB -> 2 CTAs/SM

// ---------------- prep partitioning ----------------
#define X_QUADS (TOKENS * NIN / 4)          // 262144 float4
#define X_BLOCKS (X_QUADS / 256)            // 1024
#define WARP_NZ 256                         // nz per warp (64 quads, 2 per lane)
#define NCHUNK (NSPARSE / WARP_NZ)          // 32768 warp chunks
#define S_CTAS (NCHUNK / 8)                 // 4096 scatter CTAs (8 warps each)
#define SW_CAP 1280                         // smem halves per warp window (span 512 +- 24 sigma)

// ---------------- persistent device scratch (zero-init at module load) ----------------
__device__ __half g_W[NOUT * NIN];     // 32 MB fp16 weight; untouched entries stay 0 forever
__device__ __half g_xh[TOKENS * NIN];  // 2 MB fp16 activations

// ---------------- helpers ----------------
__device__ __forceinline__ uint32_t s2u(const void* p) {
    uint32_t a;
    asm("{ .reg .u64 t; cvta.to.shared.u64 t, %1; cvt.u32.u64 %0, t; }" : "=r"(a) : "l"(p));
    return a;
}

__device__ __forceinline__ void cpasync16(uint32_t saddr, const void* g) {
    asm volatile("cp.async.cg.shared.global [%0], [%1], 16;" :: "r"(saddr), "l"(g) : "memory");
}
#define CP_COMMIT() asm volatile("cp.async.commit_group;" ::: "memory")
#define CP_WAIT()   asm volatile("cp.async.wait_group %0;" :: "n"(STAGES - 2) : "memory")

__device__ __forceinline__ void ldsm4(uint32_t& r0, uint32_t& r1, uint32_t& r2, uint32_t& r3,
                                      uint32_t addr) {
    asm volatile("ldmatrix.sync.aligned.m8n8.x4.shared.b16 {%0,%1,%2,%3}, [%4];"
                 : "=r"(r0), "=r"(r1), "=r"(r2), "=r"(r3) : "r"(addr));
}

__device__ __forceinline__ void mma16(float* d, const uint32_t* a, uint32_t b0, uint32_t b1) {
    asm volatile(
        "mma.sync.aligned.m16n8k16.row.col.f32.f16.f16.f32 "
        "{%0,%1,%2,%3}, {%4,%5,%6,%7}, {%8,%9}, {%0,%1,%2,%3};"
        : "+f"(d[0]), "+f"(d[1]), "+f"(d[2]), "+f"(d[3])
        : "r"(a[0]), "r"(a[1]), "r"(a[2]), "r"(a[3]), "r"(b0), "r"(b1));
}

// ---------------- fused prep: warp-staged W scatter (blocks first) + x convert (last) ----------------
// Blocks [0, S_CTAS): each WARP owns 256 consecutive sorted nz (2 quads per lane).
//   Sorted unique indices -> per-warp W ranges [lo,hi] disjoint & ordered, span ~512 halves.
//   Stage the span in a 1280-half smem window, then emit full 16B lines (no DRAM sector RMW).
//   Boundary 16B chunks shared with neighbor warps get per-half stores restricted to [lo,hi]
//   (element stores -> disjoint bytes -> race-free); interior zeros are true zeros (g_W is
//   persistently zero outside scattered positions, and within [lo,hi] zeros are correct).
// Blocks [S_CTAS, S_CTAS+X_BLOCKS): convert x fp32->fp16.
__global__ void __launch_bounds__(256) prep_kernel(const float4* __restrict__ x,
                                                   const float4* __restrict__ vals,
                                                   const int4* __restrict__ idx) {
    int b = blockIdx.x;
    int tid = threadIdx.x;
    if (b >= S_CTAS) {
        int i = (b - S_CTAS) * 256 + tid;
        float4 v = x[i];
        __half2* o = reinterpret_cast<__half2*>(g_xh);
        o[2 * i]     = __float22half2_rn(make_float2(v.x, v.y));
        o[2 * i + 1] = __float22half2_rn(make_float2(v.z, v.w));
        return;
    }
    __shared__ __align__(16) __half swin[8 * SW_CAP];   // 20 KB static
    int wid = tid >> 5, lane = tid & 31;
    int w = b * 8 + wid;                    // warp's global 256-nz chunk
    int q0 = w * 64 + lane;                 // this lane's first quad
    float4 v0 = vals[q0];
    float4 v1 = vals[q0 + 32];
    int4 id0 = idx[q0];
    int4 id1 = idx[q0 + 32];
    int lo = __shfl_sync(0xFFFFFFFFu, id0.x, 0);
    int hi = __shfl_sync(0xFFFFFFFFu, id1.w, 31);
    int sbase = lo & ~7;
    int span = hi - sbase + 1;
    __half* s = swin + wid * SW_CAP;

    if (span <= SW_CAP) {
        // zero only [0, span) rounded up to 16B
        int zq = ((span + 7) & ~7) >> 3;    // int4 count (<= 160)
        int4* s4 = reinterpret_cast<int4*>(s);
        int4 z = make_int4(0, 0, 0, 0);
        for (int i = lane; i < zq; i += 32) s4[i] = z;
        __syncwarp();
        s[id0.x - sbase] = __float2half_rn(v0.x);
        s[id0.y - sbase] = __float2half_rn(v0.y);
        s[id0.z - sbase] = __float2half_rn(v0.z);
        s[id0.w - sbase] = __float2half_rn(v0.w);
        s[id1.x - sbase] = __float2half_rn(v1.x);
        s[id1.y - sbase] = __float2half_rn(v1.y);
        s[id1.z - sbase] = __float2half_rn(v1.z);
        s[id1.w - sbase] = __float2half_rn(v1.w);
        __syncwarp();
        // full 16B chunks strictly inside [lo, hi+1)
        int cstart = (lo + 7) >> 3;
        int cend = (hi + 1) >> 3;
        int4* w4 = reinterpret_cast<int4*>(g_W);
        for (int ch = cstart + lane; ch < cend; ch += 32)
            w4[ch] = *reinterpret_cast<int4*>(s + (ch * 8 - sbase));
        // front partial: halves [lo, cstart*8)
        int fp = cstart * 8 - lo;           // 0..7
        if (lane < fp) g_W[lo + lane] = s[(lo - sbase) + lane];
        // back partial: halves [cend*8, hi]
        int bp = hi + 1 - cend * 8;         // 0..7
        if (lane >= 8 && lane < 8 + bp) {
            int pos = cend * 8 + (lane - 8);
            g_W[pos] = s[pos - sbase];
        }
    } else {
        // statistical impossibility fallback (keeps correctness unconditional)
        g_W[id0.x] = __float2half_rn(v0.x);
        g_W[id0.y] = __float2half_rn(v0.y);
        g_W[id0.z] = __float2half_rn(v0.z);
        g_W[id0.w] = __float2half_rn(v0.w);
        g_W[id1.x] = __float2half_rn(v1.x);
        g_W[id1.y] = __float2half_rn(v1.y);
        g_W[id1.z] = __float2half_rn(v1.z);
        g_W[id1.w] = __float2half_rn(v1.w);
    }
}

// ---------------- stage load: gmem -> swizzled smem via cp.async ----------------
__device__ __forceinline__ void load_stage(uint32_t sb, int mbase, int nbase, int stage, int tid) {
    int slot = stage & (STAGES - 1);
    int k0 = stage * BK;
    uint32_t abase = sb + slot * STAGE_BYTES;
    uint32_t bbase = abase + A_BYTES;
    #pragma unroll
    for (int i = 0; i < 4; i++) {
        int q = tid + i * NTHREADS;
        int row = q >> 3, c = q & 7;
        const __half* g = g_xh + (mbase + row) * NIN + k0 + c * 8;
        uint32_t off = row * 128 + c * 16;
        cpasync16(abase + (off ^ ((off >> 3) & 0x70)), g);
    }
    #pragma unroll
    for (int i = 0; i < 4; i++) {
        int q = tid + i * NTHREADS;
        int row = q >> 3, c = q & 7;
        const __half* g = g_W + (size_t)(nbase + row) * NIN + k0 + c * 8;
        uint32_t off = row * 128 + c * 16;
        cpasync16(bbase + (off ^ ((off >> 3) & 0x70)), g);
    }
}

// ---------------- GEMM: out[256,4096] = xh @ W^T (fp16 mma, fp32 accum) ----------------
__global__ void __launch_bounds__(NTHREADS, 2) gemm_kernel(float* __restrict__ out) {
    extern __shared__ char smem[];
    uint32_t sb = s2u(smem);
    int tid = threadIdx.x;
    int lane = tid & 31;
    int wid = tid >> 5;
    int wm = wid >> 1;
    int wn = wid & 1;
    int mbase = blockIdx.y * BM;
    int nbase = blockIdx.x * BN;

    int lr = lane & 7;
    int lq = lane >> 3;

    uint32_t arow[2], axor[2];
    #pragma unroll
    for (int mt = 0; mt < 2; mt++) {
        uint32_t r = wm * 32 + mt * 16 + (lq & 1) * 8 + lr;
        arow[mt] = r * 128;
        axor[mt] = (r & 7) << 4;
    }
    uint32_t acol = (lq >> 1) * 16;
    uint32_t brow[2], bxor[2];
    #pragma unroll
    for (int p = 0; p < 2; p++) {
        uint32_t r = wn * 32 + p * 16 + (lq >> 1) * 8 + lr;
        brow[p] = r * 128;
        bxor[p] = (r & 7) << 4;
    }
    uint32_t bcol = (lq & 1) * 16;

    float acc[2][4][4];
    #pragma unroll
    for (int mt = 0; mt < 2; mt++)
        #pragma unroll
        for (int nt = 0; nt < 4; nt++)
            #pragma unroll
            for (int j = 0; j < 4; j++) acc[mt][nt][j] = 0.0f;

    #pragma unroll
    for (int l = 0; l < STAGES - 1; l++) {
        load_stage(sb, mbase, nbase, l, tid);
        CP_COMMIT();
    }

    for (int s = 0; s < NS; s++) {
        int slot = s & (STAGES - 1);
        CP_WAIT();
        __syncthreads();

        if (s + STAGES - 1 < NS) load_stage(sb, mbase, nbase, s + STAGES - 1, tid);
        CP_COMMIT();

        uint32_t aBase = sb + slot * STAGE_BYTES;
        uint32_t bBase = aBase + A_BYTES;

        #pragma unroll
        for (int ks = 0; ks < 4; ks++) {
            uint32_t a[2][4], b[2][4];
            #pragma unroll
            for (int mt = 0; mt < 2; mt++)
                ldsm4(a[mt][0], a[mt][1], a[mt][2], a[mt][3],
                      aBase + arow[mt] + ((ks * 32 + acol) ^ axor[mt]));
            #pragma unroll
            for (int p = 0; p < 2; p++)
                ldsm4(b[p][0], b[p][1], b[p][2], b[p][3],
                      bBase + brow[p] + ((ks * 32 + bcol) ^ bxor[p]));
            #pragma unroll
            for (int mt = 0; mt < 2; mt++) {
                #pragma unroll
                for (int nt = 0; nt < 4; nt++) {
                    const uint32_t* bp = b[nt >> 1];
                    mma16(acc[mt][nt], a[mt], bp[(nt & 1) * 2], bp[(nt & 1) * 2 + 1]);
                }
            }
        }
    }

    int g = lane >> 2, tg = lane & 3;
    #pragma unroll
    for (int mt = 0; mt < 2; mt++) {
        #pragma unroll
        for (int nt = 0; nt < 4; nt++) {
            int row = mbase + wm * 32 + mt * 16 + g;
            int col = nbase + wn * 32 + nt * 8 + tg * 2;
            float2* p0 = reinterpret_cast<float2*>(out + (size_t)row * NOUT + col);
            float2* p1 = reinterpret_cast<float2*>(out + (size_t)(row + 8) * NOUT + col);
            *p0 = make_float2(acc[mt][nt][0], acc[mt][nt][1]);
            *p1 = make_float2(acc[mt][nt][2], acc[mt][nt][3]);
        }
    }
}

// ---------------- launch ----------------
extern "C" void kernel_launch(void* const* d_in, const int* in_sizes, int n_in,
                              void* d_out, int out_size) {
    const float* x    = (const float*)d_in[0];
    const float* vals = (const float*)d_in[1];
    const int*   idx  = (const int*)d_in[2];
    float* out = (float*)d_out;
    (void)in_sizes; (void)n_in; (void)out_size;

    cudaFuncSetAttribute(gemm_kernel, cudaFuncAttributeMaxDynamicSharedMemorySize, SMEM_TOTAL);

    prep_kernel<<<S_CTAS + X_BLOCKS, 256>>>((const float4*)x, (const float4*)vals,
                                            (const int4*)idx);

    dim3 grid(NOUT / BN, TOKENS / BM);    // (64, 4) = 256 CTAs, 2 resident per SM
    gemm_kernel<<<grid, NTHREADS, SMEM_TOTAL>>>(out);
}

// round 15
// speedup vs baseline: 2.0958x; 1.0007x over previous
#include <cuda_runtime.h>
#include <cuda_fp16.h>
#include <cstdint>

#define TOKENS 256
#define NOUT 4096
#define NIN 4096
#define NSPARSE 8388608

// ---------------- GEMM tiling (fp16 mma.sync m16n8k16; R5 config, near HMMA cap) ----------------
#define BM 64
#define BN 64
#define BK 64                         // halfs per K-stage = 128 bytes (one swizzle row)
#define STAGES 4
#define NS (NIN / BK)                 // 64 K-stages
#define NTHREADS 128                  // 4 warps: 2 (M) x 2 (N), warp tile 32x32

#define A_BYTES (BM * 128)            // 8 KB
#define B_BYTES (BN * 128)            // 8 KB
#define STAGE_BYTES (A_BYTES + B_BYTES)
#define SMEM_TOTAL (STAGES * STAGE_BYTES)   // 64 KB -> 2 CTAs/SM

// ---------------- prep partitioning ----------------
#define X_QUADS (TOKENS * NIN / 4)          // 262144 float4
#define WARP_NZ 256                         // nz per warp (64 quads, 2 per lane)
#define NCHUNK (NSPARSE / WARP_NZ)          // 32768 warp chunks
#define S_CTAS (NCHUNK / 8)                 // 4096 scatter CTAs (8 warps each)
#define XQ_PER_CTA (X_QUADS / S_CTAS)       // 64 x-quads converted per scatter CTA
#define SW_CAP 1280                         // smem halves per warp window (span 512 +- 24 sigma)

// ---------------- persistent device scratch (zero-init at module load) ----------------
__device__ __half g_W[NOUT * NIN];     // 32 MB fp16 weight; untouched entries stay 0 forever
__device__ __half g_xh[TOKENS * NIN];  // 2 MB fp16 activations

// ---------------- helpers ----------------
__device__ __forceinline__ uint32_t s2u(const void* p) {
    uint32_t a;
    asm("{ .reg .u64 t; cvta.to.shared.u64 t, %1; cvt.u32.u64 %0, t; }" : "=r"(a) : "l"(p));
    return a;
}

__device__ __forceinline__ void cpasync16(uint32_t saddr, const void* g) {
    asm volatile("cp.async.cg.shared.global [%0], [%1], 16;" :: "r"(saddr), "l"(g) : "memory");
}
#define CP_COMMIT() asm volatile("cp.async.commit_group;" ::: "memory")
#define CP_WAIT()   asm volatile("cp.async.wait_group %0;" :: "n"(STAGES - 2) : "memory")

__device__ __forceinline__ void ldsm4(uint32_t& r0, uint32_t& r1, uint32_t& r2, uint32_t& r3,
                                      uint32_t addr) {
    asm volatile("ldmatrix.sync.aligned.m8n8.x4.shared.b16 {%0,%1,%2,%3}, [%4];"
                 : "=r"(r0), "=r"(r1), "=r"(r2), "=r"(r3) : "r"(addr));
}

__device__ __forceinline__ void mma16(float* d, const uint32_t* a, uint32_t b0, uint32_t b1) {
    asm volatile(
        "mma.sync.aligned.m16n8k16.row.col.f32.f16.f16.f32 "
        "{%0,%1,%2,%3}, {%4,%5,%6,%7}, {%8,%9}, {%0,%1,%2,%3};"
        : "+f"(d[0]), "+f"(d[1]), "+f"(d[2]), "+f"(d[3])
        : "r"(a[0]), "r"(a[1]), "r"(a[2]), "r"(a[3]), "r"(b0), "r"(b1));
}

// ---------------- prep: x convert (fused) + warp-staged W scatter, 4096 uniform CTAs ----------------
// Each CTA: threads 0-63 first convert 64 x-quads (overlaps with other warps' idx/vals loads),
// then all 8 warps scatter. Each WARP owns 256 consecutive sorted nz (2 quads per lane).
//   Sorted unique indices -> per-warp W ranges [lo,hi] disjoint & ordered, span ~512 halves.
//   Stage the span in a 1280-half smem window, then emit full 16B lines (no DRAM sector RMW).
//   Boundary 16B chunks shared with neighbor warps get per-half stores restricted to [lo,hi]
//   (element stores -> disjoint bytes -> race-free); interior zeros are true zeros (g_W is
//   persistently zero outside scattered positions, and within [lo,hi] zeros are correct).
__global__ void __launch_bounds__(256) prep_kernel(const float4* __restrict__ x,
                                                   const float4* __restrict__ vals,
                                                   const int4* __restrict__ idx) {
    int b = blockIdx.x;
    int tid = threadIdx.x;
    __shared__ __align__(16) __half swin[8 * SW_CAP];   // 20 KB static
    int wid = tid >> 5, lane = tid & 31;

    // ---- scatter loads first (maximize MLP; convert rides under their latency) ----
    int w = b * 8 + wid;                    // warp's global 256-nz chunk
    int q0 = w * 64 + lane;                 // this lane's first quad
    float4 v0 = vals[q0];
    float4 v1 = vals[q0 + 32];
    int4 id0 = idx[q0];
    int4 id1 = idx[q0 + 32];

    // ---- fused x convert: threads 0-63, one quad each ----
    if (tid < XQ_PER_CTA) {
        int i = b * XQ_PER_CTA + tid;
        float4 v = x[i];
        __half2* o = reinterpret_cast<__half2*>(g_xh);
        o[2 * i]     = __float22half2_rn(make_float2(v.x, v.y));
        o[2 * i + 1] = __float22half2_rn(make_float2(v.z, v.w));
    }

    int lo = __shfl_sync(0xFFFFFFFFu, id0.x, 0);
    int hi = __shfl_sync(0xFFFFFFFFu, id1.w, 31);
    int sbase = lo & ~7;
    int span = hi - sbase + 1;
    __half* s = swin + wid * SW_CAP;

    if (span <= SW_CAP) {
        // zero only [0, span) rounded up to 16B
        int zq = ((span + 7) & ~7) >> 3;    // int4 count (<= 160)
        int4* s4 = reinterpret_cast<int4*>(s);
        int4 z = make_int4(0, 0, 0, 0);
        for (int i = lane; i < zq; i += 32) s4[i] = z;
        __syncwarp();
        s[id0.x - sbase] = __float2half_rn(v0.x);
        s[id0.y - sbase] = __float2half_rn(v0.y);
        s[id0.z - sbase] = __float2half_rn(v0.z);
        s[id0.w - sbase] = __float2half_rn(v0.w);
        s[id1.x - sbase] = __float2half_rn(v1.x);
        s[id1.y - sbase] = __float2half_rn(v1.y);
        s[id1.z - sbase] = __float2half_rn(v1.z);
        s[id1.w - sbase] = __float2half_rn(v1.w);
        __syncwarp();
        // full 16B chunks strictly inside [lo, hi+1)
        int cstart = (lo + 7) >> 3;
        int cend = (hi + 1) >> 3;
        int4* w4 = reinterpret_cast<int4*>(g_W);
        for (int ch = cstart + lane; ch < cend; ch += 32)
            w4[ch] = *reinterpret_cast<int4*>(s + (ch * 8 - sbase));
        // front partial: halves [lo, cstart*8)
        int fp = cstart * 8 - lo;           // 0..7
        if (lane < fp) g_W[lo + lane] = s[(lo - sbase) + lane];
        // back partial: halves [cend*8, hi]
        int bp = hi + 1 - cend * 8;         // 0..7
        if (lane >= 8 && lane < 8 + bp) {
            int pos = cend * 8 + (lane - 8);
            g_W[pos] = s[pos - sbase];
        }
    } else {
        // statistical impossibility fallback (keeps correctness unconditional)
        g_W[id0.x] = __float2half_rn(v0.x);
        g_W[id0.y] = __float2half_rn(v0.y);
        g_W[id0.z] = __float2half_rn(v0.z);
        g_W[id0.w] = __float2half_rn(v0.w);
        g_W[id1.x] = __float2half_rn(v1.x);
        g_W[id1.y] = __float2half_rn(v1.y);
        g_W[id1.z] = __float2half_rn(v1.z);
        g_W[id1.w] = __float2half_rn(v1.w);
    }
}

// ---------------- stage load: gmem -> swizzled smem via cp.async ----------------
__device__ __forceinline__ void load_stage(uint32_t sb, int mbase, int nbase, int stage, int tid) {
    int slot = stage & (STAGES - 1);
    int k0 = stage * BK;
    uint32_t abase = sb + slot * STAGE_BYTES;
    uint32_t bbase = abase + A_BYTES;
    #pragma unroll
    for (int i = 0; i < 4; i++) {
        int q = tid + i * NTHREADS;
        int row = q >> 3, c = q & 7;
        const __half* g = g_xh + (mbase + row) * NIN + k0 + c * 8;
        uint32_t off = row * 128 + c * 16;
        cpasync16(abase + (off ^ ((off >> 3) & 0x70)), g);
    }
    #pragma unroll
    for (int i = 0; i < 4; i++) {
        int q = tid + i * NTHREADS;
        int row = q >> 3, c = q & 7;
        const __half* g = g_W + (size_t)(nbase + row) * NIN + k0 + c * 8;
        uint32_t off = row * 128 + c * 16;
        cpasync16(bbase + (off ^ ((off >> 3) & 0x70)), g);
    }
}

// ---------------- GEMM: out[256,4096] = xh @ W^T (fp16 mma, fp32 accum) ----------------
__global__ void __launch_bounds__(NTHREADS, 2) gemm_kernel(float* __restrict__ out) {
    extern __shared__ char smem[];
    uint32_t sb = s2u(smem);
    int tid = threadIdx.x;
    int lane = tid & 31;
    int wid = tid >> 5;
    int wm = wid >> 1;
    int wn = wid & 1;
    int mbase = blockIdx.y * BM;
    int nbase = blockIdx.x * BN;

    int lr = lane & 7;
    int lq = lane >> 3;

    uint32_t arow[2], axor[2];
    #pragma unroll
    for (int mt = 0; mt < 2; mt++) {
        uint32_t r = wm * 32 + mt * 16 + (lq & 1) * 8 + lr;
        arow[mt] = r * 128;
        axor[mt] = (r & 7) << 4;
    }
    uint32_t acol = (lq >> 1) * 16;
    uint32_t brow[2], bxor[2];
    #pragma unroll
    for (int p = 0; p < 2; p++) {
        uint32_t r = wn * 32 + p * 16 + (lq >> 1) * 8 + lr;
        brow[p] = r * 128;
        bxor[p] = (r & 7) << 4;
    }
    uint32_t bcol = (lq & 1) * 16;

    float acc[2][4][4];
    #pragma unroll
    for (int mt = 0; mt < 2; mt++)
        #pragma unroll
        for (int nt = 0; nt < 4; nt++)
            #pragma unroll
            for (int j = 0; j < 4; j++) acc[mt][nt][j] = 0.0f;

    #pragma unroll
    for (int l = 0; l < STAGES - 1; l++) {
        load_stage(sb, mbase, nbase, l, tid);
        CP_COMMIT();
    }

    for (int s = 0; s < NS; s++) {
        int slot = s & (STAGES - 1);
        CP_WAIT();
        __syncthreads();

        if (s + STAGES - 1 < NS) load_stage(sb, mbase, nbase, s + STAGES - 1, tid);
        CP_COMMIT();

        uint32_t aBase = sb + slot * STAGE_BYTES;
        uint32_t bBase = aBase + A_BYTES;

        #pragma unroll
        for (int ks = 0; ks < 4; ks++) {
            uint32_t a[2][4], b[2][4];
            #pragma unroll
            for (int mt = 0; mt < 2; mt++)
                ldsm4(a[mt][0], a[mt][1], a[mt][2], a[mt][3],
                      aBase + arow[mt] + ((ks * 32 + acol) ^ axor[mt]));
            #pragma unroll
            for (int p = 0; p < 2; p++)
                ldsm4(b[p][0], b[p][1], b[p][2], b[p][3],
                      bBase + brow[p] + ((ks * 32 + bcol) ^ bxor[p]));
            #pragma unroll
            for (int mt = 0; mt < 2; mt++) {
                #pragma unroll
                for (int nt = 0; nt < 4; nt++) {
                    const uint32_t* bp = b[nt >> 1];
                    mma16(acc[mt][nt], a[mt], bp[(nt & 1) * 2], bp[(nt & 1) * 2 + 1]);
                }
            }
        }
    }

    int g = lane >> 2, tg = lane & 3;
    #pragma unroll
    for (int mt = 0; mt < 2; mt++) {
        #pragma unroll
        for (int nt = 0; nt < 4; nt++) {
            int row = mbase + wm * 32 + mt * 16 + g;
            int col = nbase + wn * 32 + nt * 8 + tg * 2;
            float2* p0 = reinterpret_cast<float2*>(out + (size_t)row * NOUT + col);
            float2* p1 = reinterpret_cast<float2*>(out + (size_t)(row + 8) * NOUT + col);
            *p0 = make_float2(acc[mt][nt][0], acc[mt][nt][1]);
            *p1 = make_float2(acc[mt][nt][2], acc[mt][nt][3]);
        }
    }
}

// ---------------- launch ----------------
extern "C" void kernel_launch(void* const* d_in, const int* in_sizes, int n_in,
                              void* d_out, int out_size) {
    const float* x    = (const float*)d_in[0];
    const float* vals = (const float*)d_in[1];
    const int*   idx  = (const int*)d_in[2];
    float* out = (float*)d_out;
    (void)in_sizes; (void)n_in; (void)out_size;

    cudaFuncSetAttribute(gemm_kernel, cudaFuncAttributeMaxDynamicSharedMemorySize, SMEM_TOTAL);

    prep_kernel<<<S_CTAS, 256>>>((const float4*)x, (const float4*)vals, (const int4*)idx);

    dim3 grid(NOUT / BN, TOKENS / BM);    // (64, 4) = 256 CTAs, 2 resident per SM
    gemm_kernel<<<grid, NTHREADS, SMEM_TOTAL>>>(out);
}